// round 8
// baseline (speedup 1.0000x reference)
#include <cuda_runtime.h>
#include <math_constants.h>
#include <cstdint>

#define NROWS 100000
#define DIM   1024
#define RNUM  64

#define SEG        1024
#define NSEG_CKPT  97          // boundaries at rows 1024..99328

// argmax stage-1: 250 blocks x 400 rows
#define AB 250
#define AROWS 400

// dots: 128 rows per block, 64-col chunks
#define DR 128
#define DCH 64
#define DBLK ((NROWS + DR - 1) / DR)    // 782

// -------- scratch (no allocations allowed) --------
__device__ float g_ckpt[NSEG_CKPT][DIM];  // chain state after rows [0,(s+1)*SEG)
__device__ float g_m[DIM];
__device__ float g_score[NROWS];
__device__ float g_taken[NROWS];
__device__ int   g_takenList[RNUM];       // sorted ascending, distinct taken rows
__device__ int   g_nTaken;
__device__ int   g_remaining;
__device__ int   g_restartSeg;            // first segment whose chain changed
__device__ float g_bScore[AB];
__device__ int   g_bIdx[AB];
__device__ int   g_sel[RNUM];
__device__ int   g_selSorted[RNUM];

// -------- init (graph replays must fully reset state) --------
__global__ void init_kernel() {
    int i = blockIdx.x * blockDim.x + threadIdx.x;
    if (i < NROWS) g_taken[i] = 0.0f;
    if (i == 0) { g_remaining = NROWS; g_nTaken = 0; g_restartSeg = 0; }
}

// -------- sequential column-sum chain (validated in R7) --------
// Thread = one column. acc_{r+1} = fadd(acc_r, x[r,c]) in strict row order,
// skipping taken rows (bit-identical to fma(x, mask, acc) with mask in {0,1}).
// Restart from checkpointed segment; refresh downstream checkpoints.
__global__ void __launch_bounds__(256) colsum_kernel(const float* __restrict__ x) {
    int c = blockIdx.x * 256 + threadIdx.x;      // gridDim.x = 4

    __shared__ int sList[RNUM];
    __shared__ int sN, sSeg, sRem;
    if (threadIdx.x == 0) { sN = g_nTaken; sSeg = g_restartSeg; sRem = g_remaining; }
    __syncthreads();
    if (threadIdx.x < RNUM && threadIdx.x < sN) sList[threadIdx.x] = g_takenList[threadIdx.x];
    __syncthreads();

    int s0 = sSeg;
    int rStart = s0 << 10;
    float acc = (s0 == 0) ? 0.0f : g_ckpt[s0 - 1][c];

    int p = 0;
    while (p < sN && sList[p] < rStart) p++;
    int nxt = (p < sN) ? sList[p] : 0x7fffffff;

#pragma unroll 4
    for (int r = rStart; r < NROWS; ++r) {
        float v = x[(size_t)r * DIM + c];
        if (r == nxt) {
            p++;
            nxt = (p < sN) ? sList[p] : 0x7fffffff;
        } else {
            acc = __fadd_rn(acc, v);
        }
        if (((r + 1) & (SEG - 1)) == 0)
            g_ckpt[((r + 1) >> 10) - 1][c] = acc;
    }
    g_m[c] = __fdiv_rn(acc, (float)sRem);
}

// -------- dots: Eigen row-major gemv emulation (NEON width 4) --------------
// Per row: 4 interleaved FMA chains, lane l accumulates j ≡ l (mod 4) in
// increasing j: acc_l = fma(x[j], m[j], acc_l). Combine = vaddvq_f32:
// (a0+a1)+(a2+a3). One thread per row; smem tiling keeps loads coalesced.
__global__ void __launch_bounds__(DR, 4) dots_kernel(const float* __restrict__ x) {
    __shared__ float tile[DR][DCH + 1];
    __shared__ float ms[DCH];

    int t = threadIdx.x;
    int row0 = blockIdx.x * DR;
    int myRow = row0 + t;

    float a0 = 0.0f, a1 = 0.0f, a2 = 0.0f, a3 = 0.0f;

    for (int cb = 0; cb < DIM / DCH; cb++) {
        // coalesced tile load: 128 rows x 64 cols
        for (int i = t; i < DR * DCH; i += DR) {
            int r = i >> 6;          // i / 64
            int c = i & (DCH - 1);
            int gr = row0 + r;
            tile[r][c] = (gr < NROWS) ? x[(size_t)gr * DIM + cb * DCH + c] : 0.0f;
        }
        if (t < DCH) ms[t] = g_m[cb * DCH + t];
        __syncthreads();

        if (myRow < NROWS) {
#pragma unroll
            for (int c = 0; c < DCH; c += 4) {
                a0 = __fmaf_rn(tile[t][c + 0], ms[c + 0], a0);
                a1 = __fmaf_rn(tile[t][c + 1], ms[c + 1], a1);
                a2 = __fmaf_rn(tile[t][c + 2], ms[c + 2], a2);
                a3 = __fmaf_rn(tile[t][c + 3], ms[c + 3], a3);
            }
        }
        __syncthreads();
    }

    if (myRow < NROWS) {
        float dot = __fadd_rn(__fadd_rn(a0, a1), __fadd_rn(a2, a3));
        g_score[myRow] = __fadd_rn(__fdiv_rn(1.0f, dot), g_taken[myRow]);
    }
}

// -------- argmax stage 1 (first-index ties) --------
__global__ void argmax1_kernel() {
    __shared__ float sSc[256];
    __shared__ int   sIx[256];
    int base = blockIdx.x * AROWS;

    float best = -CUDART_INF_F;
    int   bi = 0x7fffffff;
    for (int i = threadIdx.x; i < AROWS; i += 256) {
        int r = base + i;
        float s = g_score[r];
        if (s > best || (s == best && r < bi)) { best = s; bi = r; }
    }
    sSc[threadIdx.x] = best;
    sIx[threadIdx.x] = bi;
    __syncthreads();
    for (int off = 128; off > 0; off >>= 1) {
        if (threadIdx.x < off) {
            float s = sSc[threadIdx.x + off];
            int  id = sIx[threadIdx.x + off];
            if (s > sSc[threadIdx.x] || (s == sSc[threadIdx.x] && id < sIx[threadIdx.x])) {
                sSc[threadIdx.x] = s;
                sIx[threadIdx.x] = id;
            }
        }
        __syncthreads();
    }
    if (threadIdx.x == 0) { g_bScore[blockIdx.x] = sSc[0]; g_bIdx[blockIdx.x] = sIx[0]; }
}

// -------- finalize: global argmax; maintain taken list / restart segment ----
__global__ void finalize_kernel(int k) {
    __shared__ float sSc[256];
    __shared__ int   sIx[256];

    float best = -CUDART_INF_F;
    int   bi = 0x7fffffff;
    for (int i = threadIdx.x; i < AB; i += 256) {
        float s = g_bScore[i];
        int  id = g_bIdx[i];
        if (s > best || (s == best && id < bi)) { best = s; bi = id; }
    }
    sSc[threadIdx.x] = best;
    sIx[threadIdx.x] = bi;
    __syncthreads();
    for (int off = 128; off > 0; off >>= 1) {
        if (threadIdx.x < off) {
            float s = sSc[threadIdx.x + off];
            int  id = sIx[threadIdx.x + off];
            if (s > sSc[threadIdx.x] || (s == sSc[threadIdx.x] && id < sIx[threadIdx.x])) {
                sSc[threadIdx.x] = s;
                sIx[threadIdx.x] = id;
            }
        }
        __syncthreads();
    }
    if (threadIdx.x == 0) {
        int w = sIx[0];
        g_sel[k] = w;
        float t = g_taken[w];
        g_taken[w] = __fadd_rn(t, -100000.0f);
        if (t == 0.0f) {
            g_remaining -= 1;
            int n = g_nTaken;
            int pos = n;
            while (pos > 0 && g_takenList[pos - 1] > w) {
                g_takenList[pos] = g_takenList[pos - 1];
                pos--;
            }
            g_takenList[pos] = w;
            g_nTaken = n + 1;
        }
        g_restartSeg = w >> 10;   // chain changes from row w onward
    }
}

// -------- epilogue: rank sort (duplicate-safe), gather rows --------
__global__ void sortsel_kernel() {
    int t = threadIdx.x;            // 64 threads
    int v = g_sel[t];
    int r = 0;
    for (int j = 0; j < RNUM; j++) {
        int u = g_sel[j];
        r += (u < v) || (u == v && j < t);
    }
    g_selSorted[r] = v;
}

__global__ void gather_kernel(const float* __restrict__ x, float* __restrict__ out) {
    int row = g_selSorted[blockIdx.x];
    const float4* src = (const float4*)(x + (size_t)row * DIM);
    float4* dst = (float4*)(out + (size_t)blockIdx.x * DIM);
    dst[threadIdx.x] = src[threadIdx.x];   // 256 threads x float4 = 1024 floats
}

extern "C" void kernel_launch(void* const* d_in, const int* in_sizes, int n_in,
                              void* d_out, int out_size) {
    const float* x = (const float*)d_in[0];
    float* out = (float*)d_out;

    init_kernel<<<(NROWS + 255) / 256, 256>>>();

    for (int k = 0; k < RNUM; k++) {
        colsum_kernel<<<DIM / 256, 256>>>(x);
        dots_kernel<<<DBLK, DR>>>(x);
        argmax1_kernel<<<AB, 256>>>();
        finalize_kernel<<<1, 256>>>(k);
    }

    sortsel_kernel<<<1, RNUM>>>();
    gather_kernel<<<RNUM, 256>>>(x, out);
}

// round 9
// speedup vs baseline: 11.9371x; 11.9371x over previous
#include <cuda_runtime.h>
#include <math_constants.h>
#include <cstdint>

#define NROWS 100000
#define DIM   1024
#define RNUM  64

#define SEG        1024
#define NSEG_CKPT  97          // boundaries at rows 1024..99328

// colsum pipeline: 32 blocks x 32 cols, 64-row tiles, 5-stage cp.async ring
#define CS_BLOCKS 32
#define CS_COLS   32
#define CS_T      64
#define CS_S      5

// dots: 256 rows per block, 32-col chunks
#define DR   256
#define DCH  32
#define DBLK ((NROWS + DR - 1) / DR)    // 391

// -------- scratch (no allocations allowed) --------
__device__ float g_ckpt[NSEG_CKPT][DIM];  // chain state after rows [0,(s+1)*SEG)
__device__ float g_m[DIM];
__device__ float g_taken[NROWS];
__device__ int   g_takenList[RNUM];       // sorted ascending, distinct taken rows
__device__ int   g_nTaken;
__device__ int   g_remaining;
__device__ int   g_restartSeg;            // first segment whose chain changed
__device__ float g_bScore[DBLK];
__device__ int   g_bIdx[DBLK];
__device__ int   g_sel[RNUM];
__device__ int   g_selSorted[RNUM];

// -------- init (graph replays must fully reset state) --------
__global__ void init_kernel() {
    int i = blockIdx.x * blockDim.x + threadIdx.x;
    if (i < NROWS) g_taken[i] = 0.0f;
    if (i == 0) { g_remaining = NROWS; g_nTaken = 0; g_restartSeg = 0; }
}

__device__ __forceinline__ void cp_async16(uint32_t saddr, const float* gptr) {
    asm volatile("cp.async.ca.shared.global [%0], [%1], 16;" :: "r"(saddr), "l"(gptr));
}

// issue one tile's cp.async ops: 64 rows x 128B = 512 x 16B, 4 per thread
__device__ __forceinline__ void cs_issue(const float* __restrict__ x, uint32_t bufAddr,
                                         int rStart, int ti, int colBase, int t) {
    int r0 = rStart + ti * CS_T;
    int st = ti % CS_S;
#pragma unroll
    for (int o = 0; o < 4; o++) {
        int op  = t + o * 128;
        int row = op >> 3;
        int s16 = op & 7;
        int gr = r0 + row;
        if (gr < NROWS) {
            uint32_t sa = bufAddr + (uint32_t)(((st * CS_T + row) * CS_COLS + s16 * 4) * 4);
            cp_async16(sa, x + (size_t)gr * DIM + colBase + s16 * 4);
        }
    }
}

// -------- colsum: bit-exact sequential fadd chain per column (validated R8),
// now fed by a 5-stage cp.async pipeline. Warp 0 = chain consumers. ---------
__global__ void __launch_bounds__(128) colsum_kernel(const float* __restrict__ x) {
    __shared__ float buf[CS_S][CS_T][CS_COLS];   // 40 KB
    __shared__ int sList[RNUM];
    __shared__ int sMeta[3];                      // n, seg, rem

    int t = threadIdx.x;
    if (t == 0) { sMeta[0] = g_nTaken; sMeta[1] = g_restartSeg; sMeta[2] = g_remaining; }
    __syncthreads();
    int sN = sMeta[0], sSeg = sMeta[1], sRem = sMeta[2];
    if (t < RNUM && t < sN) sList[t] = g_takenList[t];
    __syncthreads();

    int colBase = blockIdx.x * CS_COLS;
    int rStart = sSeg << 10;
    int ntiles = (NROWS - rStart + CS_T - 1) / CS_T;   // >= 11 always

    uint32_t bufAddr = (uint32_t)__cvta_generic_to_shared(&buf[0][0][0]);

    // prologue: stages 0..3 in flight
#pragma unroll
    for (int ti = 0; ti < CS_S - 1; ti++) {
        cs_issue(x, bufAddr, rStart, ti, colBase, t);
        asm volatile("cp.async.commit_group;");
    }

    float acc = 0.0f;
    int p = 0, nxt = 0x7fffffff;
    if (t < CS_COLS) {
        if (sSeg > 0) acc = g_ckpt[sSeg - 1][colBase + t];
        while (p < sN && sList[p] < rStart) p++;
        nxt = (p < sN) ? sList[p] : 0x7fffffff;
    }

    for (int i = 0; i < ntiles; i++) {
        asm volatile("cp.async.wait_group 3;");
        __syncthreads();                       // tile i ready; compute of i-1 done
        if (i + CS_S - 1 < ntiles)
            cs_issue(x, bufAddr, rStart, i + CS_S - 1, colBase, t);
        asm volatile("cp.async.commit_group;");   // empty group ok at tail

        if (t < CS_COLS) {
            int st = i % CS_S;
            int r0 = rStart + i * CS_T;
            int nr = min(CS_T, NROWS - r0);
            for (int base = 0; base < nr; base += 16) {
                float v[16];
#pragma unroll
                for (int j = 0; j < 16; j++)
                    v[j] = (base + j < nr) ? buf[st][base + j][t] : 0.0f;
#pragma unroll
                for (int j = 0; j < 16; j++) {
                    if (base + j < nr) {
                        int r = r0 + base + j;
                        if (r == nxt) { p++; nxt = (p < sN) ? sList[p] : 0x7fffffff; }
                        else acc = __fadd_rn(acc, v[j]);
                        if (((r + 1) & (SEG - 1)) == 0)
                            g_ckpt[((r + 1) >> 10) - 1][colBase + t] = acc;
                    }
                }
            }
        }
    }
    asm volatile("cp.async.wait_group 0;");
    if (t < CS_COLS)
        g_m[colBase + t] = __fdiv_rn(acc, (float)sRem);
}

// -------- dots + block argmax: Eigen 4-chain FMA order (validated R8) -------
__global__ void __launch_bounds__(DR) dots_argmax_kernel(const float* __restrict__ x) {
    __shared__ float tile[DR][DCH + 1];      // stride 33: conflict-free
    __shared__ float ms[DCH];
    __shared__ float sSc[DR];
    __shared__ int   sIx[DR];

    int t = threadIdx.x;
    int row0 = blockIdx.x * DR;
    int row = row0 + t;
    bool valid = row < NROWS;

    float a0 = 0.0f, a1 = 0.0f, a2 = 0.0f, a3 = 0.0f;

    for (int cb = 0; cb < DIM / DCH; cb++) {
        for (int i = t; i < DR * DCH; i += DR) {
            int r = i >> 5;
            int c = i & (DCH - 1);
            int gr = row0 + r;
            tile[r][c] = (gr < NROWS) ? x[(size_t)gr * DIM + cb * DCH + c] : 0.0f;
        }
        if (t < DCH) ms[t] = g_m[cb * DCH + t];
        __syncthreads();
        if (valid) {
#pragma unroll
            for (int c = 0; c < DCH; c += 4) {
                a0 = __fmaf_rn(tile[t][c + 0], ms[c + 0], a0);
                a1 = __fmaf_rn(tile[t][c + 1], ms[c + 1], a1);
                a2 = __fmaf_rn(tile[t][c + 2], ms[c + 2], a2);
                a3 = __fmaf_rn(tile[t][c + 3], ms[c + 3], a3);
            }
        }
        __syncthreads();
    }

    float score = -CUDART_INF_F;
    if (valid) {
        float dot = __fadd_rn(__fadd_rn(a0, a1), __fadd_rn(a2, a3));
        score = __fadd_rn(__fdiv_rn(1.0f, dot), g_taken[row]);
    }
    sSc[t] = score;
    sIx[t] = row;
    __syncthreads();
    for (int off = DR / 2; off > 0; off >>= 1) {
        if (t < off) {
            float s = sSc[t + off];
            int  id = sIx[t + off];
            if (s > sSc[t] || (s == sSc[t] && id < sIx[t])) { sSc[t] = s; sIx[t] = id; }
        }
        __syncthreads();
    }
    if (t == 0) { g_bScore[blockIdx.x] = sSc[0]; g_bIdx[blockIdx.x] = sIx[0]; }
}

// -------- finalize: global argmax over 391 blocks; maintain taken state -----
__global__ void finalize_kernel(int k) {
    __shared__ float sSc[256];
    __shared__ int   sIx[256];

    float best = -CUDART_INF_F;
    int   bi = 0x7fffffff;
    for (int i = threadIdx.x; i < DBLK; i += 256) {
        float s = g_bScore[i];
        int  id = g_bIdx[i];
        if (s > best || (s == best && id < bi)) { best = s; bi = id; }
    }
    sSc[threadIdx.x] = best;
    sIx[threadIdx.x] = bi;
    __syncthreads();
    for (int off = 128; off > 0; off >>= 1) {
        if (threadIdx.x < off) {
            float s = sSc[threadIdx.x + off];
            int  id = sIx[threadIdx.x + off];
            if (s > sSc[threadIdx.x] || (s == sSc[threadIdx.x] && id < sIx[threadIdx.x])) {
                sSc[threadIdx.x] = s;
                sIx[threadIdx.x] = id;
            }
        }
        __syncthreads();
    }
    if (threadIdx.x == 0) {
        int w = sIx[0];
        g_sel[k] = w;
        float t = g_taken[w];
        g_taken[w] = __fadd_rn(t, -100000.0f);
        if (t == 0.0f) {
            g_remaining -= 1;
            int n = g_nTaken;
            int pos = n;
            while (pos > 0 && g_takenList[pos - 1] > w) {
                g_takenList[pos] = g_takenList[pos - 1];
                pos--;
            }
            g_takenList[pos] = w;
            g_nTaken = n + 1;
        }
        g_restartSeg = w >> 10;   // chain changes from row w onward
    }
}

// -------- epilogue: rank sort (duplicate-safe), gather rows --------
__global__ void sortsel_kernel() {
    int t = threadIdx.x;            // 64 threads
    int v = g_sel[t];
    int r = 0;
    for (int j = 0; j < RNUM; j++) {
        int u = g_sel[j];
        r += (u < v) || (u == v && j < t);
    }
    g_selSorted[r] = v;
}

__global__ void gather_kernel(const float* __restrict__ x, float* __restrict__ out) {
    int row = g_selSorted[blockIdx.x];
    const float4* src = (const float4*)(x + (size_t)row * DIM);
    float4* dst = (float4*)(out + (size_t)blockIdx.x * DIM);
    dst[threadIdx.x] = src[threadIdx.x];   // 256 threads x float4 = 1024 floats
}

extern "C" void kernel_launch(void* const* d_in, const int* in_sizes, int n_in,
                              void* d_out, int out_size) {
    const float* x = (const float*)d_in[0];
    float* out = (float*)d_out;

    init_kernel<<<(NROWS + 255) / 256, 256>>>();

    for (int k = 0; k < RNUM; k++) {
        colsum_kernel<<<CS_BLOCKS, 128>>>(x);
        dots_argmax_kernel<<<DBLK, DR>>>(x);
        finalize_kernel<<<1, 256>>>(k);
    }

    sortsel_kernel<<<1, RNUM>>>();
    gather_kernel<<<RNUM, 256>>>(x, out);
}

// round 10
// speedup vs baseline: 65.2399x; 5.4653x over previous
#include <cuda_runtime.h>
#include <math_constants.h>
#include <cstdint>

#define NROWS 100000
#define DIM   1024
#define RNUM  64

#define SEG        1024
#define NSEG_CKPT  97          // boundaries at rows 1024..99328

// colsum pipeline: 32 blocks x 32 cols, 256-row tiles, 4-stage cp.async ring
#define CS_BLOCKS 32
#define CS_COLS   32
#define CS_T      256
#define CS_S      4
#define CS_SMEM   (CS_S * CS_T * CS_COLS * 4)   // 128 KB dynamic

// dots: 256 rows per block, 32-col chunks
#define DR   256
#define DCH  32
#define DBLK ((NROWS + DR - 1) / DR)    // 391

// -------- scratch (no allocations allowed) --------
__device__ float g_ckpt[NSEG_CKPT][DIM];  // chain state after rows [0,(s+1)*SEG)
__device__ float g_m[DIM];
__device__ float g_taken[NROWS];
__device__ int   g_takenList[RNUM];       // sorted ascending, distinct taken rows
__device__ int   g_nTaken;
__device__ int   g_remaining;
__device__ int   g_restartSeg;            // first segment whose chain changed
__device__ float g_bScore[DBLK];
__device__ int   g_bIdx[DBLK];
__device__ int   g_sel[RNUM];
__device__ int   g_selSorted[RNUM];

// -------- init (graph replays must fully reset state) --------
__global__ void init_kernel() {
    int i = blockIdx.x * blockDim.x + threadIdx.x;
    if (i < NROWS) g_taken[i] = 0.0f;
    if (i == 0) { g_remaining = NROWS; g_nTaken = 0; g_restartSeg = 0; }
}

__device__ __forceinline__ void cp_async16(uint32_t saddr, const float* gptr) {
    asm volatile("cp.async.ca.shared.global [%0], [%1], 16;" :: "r"(saddr), "l"(gptr));
}

// producers (threads 32..255): issue one 256-row x 32-col tile (2048 x 16B)
__device__ __forceinline__ void cs_issue(const float* __restrict__ x, uint32_t bufAddr,
                                         int rStart, int ti, int colBase, int t) {
    int r0 = rStart + ti * CS_T;
    int st = ti & (CS_S - 1);
    uint32_t stBase = bufAddr + (uint32_t)(st * CS_T * CS_COLS * 4);
    int p = t - 32;                       // 0..223
#pragma unroll 3
    for (int op = p; op < CS_T * 8; op += 224) {
        int row = op >> 3;
        int ch  = op & 7;
        int gr = r0 + row;
        if (gr < NROWS)
            cp_async16(stBase + (uint32_t)((row * CS_COLS + ch * 4) * 4),
                       x + (size_t)gr * DIM + colBase + ch * 4);
    }
}

// -------- colsum: bit-exact sequential fadd chain per column (validated R8/R9),
// warp-specialized: warps 1-7 produce via cp.async ring, warp 0 = 32 chains. --
__global__ void __launch_bounds__(256) colsum_kernel(const float* __restrict__ x) {
    extern __shared__ float buf[];               // [CS_S][CS_T][CS_COLS]
    __shared__ int sList[RNUM];
    __shared__ int sMeta[3];

    int t = threadIdx.x;
    if (t == 0) { sMeta[0] = g_nTaken; sMeta[1] = g_restartSeg; sMeta[2] = g_remaining; }
    __syncthreads();
    int sN = sMeta[0], sSeg = sMeta[1], sRem = sMeta[2];
    if (t < RNUM && t < sN) sList[t] = g_takenList[t];
    __syncthreads();

    int colBase = blockIdx.x * CS_COLS;
    int rStart = sSeg << 10;
    int ntiles = (NROWS - rStart + CS_T - 1) / CS_T;   // >= 3 always (tail >= 672 rows)

    uint32_t bufAddr = (uint32_t)__cvta_generic_to_shared(buf);
    bool producer = (t >= 32);

    // prologue: tiles 0..2 in flight
#pragma unroll
    for (int ti = 0; ti < CS_S - 1; ti++) {
        if (producer && ti < ntiles) cs_issue(x, bufAddr, rStart, ti, colBase, t);
        asm volatile("cp.async.commit_group;");
    }

    // consumer chain state (lanes 0..31 of warp 0)
    float acc = 0.0f;
    int p = 0, nxt = 0x7fffffff;
    if (t < CS_COLS) {
        if (sSeg > 0) acc = g_ckpt[sSeg - 1][colBase + t];
        while (p < sN && sList[p] < rStart) p++;
        nxt = (p < sN) ? sList[p] : 0x7fffffff;
    }

    for (int i = 0; i < ntiles; i++) {
        asm volatile("cp.async.wait_group 2;");  // tile i complete
        __syncthreads();
        if (producer && (i + CS_S - 1) < ntiles)
            cs_issue(x, bufAddr, rStart, i + CS_S - 1, colBase, t);
        asm volatile("cp.async.commit_group;");

        if (t < CS_COLS) {
            const float* s = buf + (i & (CS_S - 1)) * CS_T * CS_COLS + t;
            int r0 = rStart + i * CS_T;
            int nr = min(CS_T, NROWS - r0);
            bool slow = (nr < CS_T) || (nxt < r0 + nr);
            if (!slow) {
                // pure chain, software-pipelined 16-row register batches
                float v0[16], v1[16];
#define LOADB(arr, b) { _Pragma("unroll") \
    for (int j = 0; j < 16; j++) arr[j] = s[(((b) << 4) + j) * CS_COLS]; }
#define CHAINB(arr) { _Pragma("unroll") \
    for (int j = 0; j < 16; j++) acc = __fadd_rn(acc, arr[j]); }
                LOADB(v0, 0)
#pragma unroll
                for (int b = 0; b < CS_T / 16; b++) {
                    if (b & 1) { if (b + 1 < CS_T / 16) LOADB(v0, b + 1) CHAINB(v1) }
                    else       { if (b + 1 < CS_T / 16) LOADB(v1, b + 1) CHAINB(v0) }
                }
                if (((r0 + CS_T) & (SEG - 1)) == 0)
                    g_ckpt[((r0 + CS_T) >> 10) - 1][colBase + t] = acc;
            } else {
                for (int j = 0; j < nr; j++) {
                    int r = r0 + j;
                    float v = s[j * CS_COLS];
                    if (r == nxt) { p++; nxt = (p < sN) ? sList[p] : 0x7fffffff; }
                    else acc = __fadd_rn(acc, v);
                    if (((r + 1) & (SEG - 1)) == 0)
                        g_ckpt[((r + 1) >> 10) - 1][colBase + t] = acc;
                }
            }
        }
        __syncthreads();
    }
    asm volatile("cp.async.wait_group 0;");
    if (t < CS_COLS)
        g_m[colBase + t] = __fdiv_rn(acc, (float)sRem);
}

// -------- dots + block argmax: Eigen 4-chain FMA order (validated R8/R9) ----
__global__ void __launch_bounds__(DR) dots_argmax_kernel(const float* __restrict__ x) {
    __shared__ float tile[DR][DCH + 1];      // stride 33: conflict-free
    __shared__ float ms[DCH];
    __shared__ float sSc[DR];
    __shared__ int   sIx[DR];

    int t = threadIdx.x;
    int row0 = blockIdx.x * DR;
    int row = row0 + t;
    bool valid = row < NROWS;

    float a0 = 0.0f, a1 = 0.0f, a2 = 0.0f, a3 = 0.0f;

    for (int cb = 0; cb < DIM / DCH; cb++) {
        // load 256 rows x 32 cols as float4 (8 per thread), coalesced
#pragma unroll
        for (int f = 0; f < 8; f++) {
            int idx = t + f * DR;
            int r = idx >> 3;
            int c4 = idx & 7;
            int gr = row0 + r;
            float4 v = make_float4(0.f, 0.f, 0.f, 0.f);
            if (gr < NROWS)
                v = ((const float4*)(x + (size_t)gr * DIM + cb * DCH))[c4];
            tile[r][c4 * 4 + 0] = v.x;
            tile[r][c4 * 4 + 1] = v.y;
            tile[r][c4 * 4 + 2] = v.z;
            tile[r][c4 * 4 + 3] = v.w;
        }
        if (t < DCH) ms[t] = g_m[cb * DCH + t];
        __syncthreads();
        if (valid) {
#pragma unroll
            for (int c = 0; c < DCH; c += 4) {
                a0 = __fmaf_rn(tile[t][c + 0], ms[c + 0], a0);
                a1 = __fmaf_rn(tile[t][c + 1], ms[c + 1], a1);
                a2 = __fmaf_rn(tile[t][c + 2], ms[c + 2], a2);
                a3 = __fmaf_rn(tile[t][c + 3], ms[c + 3], a3);
            }
        }
        __syncthreads();
    }

    float score = -CUDART_INF_F;
    if (valid) {
        float dot = __fadd_rn(__fadd_rn(a0, a1), __fadd_rn(a2, a3));
        score = __fadd_rn(__fdiv_rn(1.0f, dot), g_taken[row]);
    }
    sSc[t] = score;
    sIx[t] = row;
    __syncthreads();
    for (int off = DR / 2; off > 0; off >>= 1) {
        if (t < off) {
            float s = sSc[t + off];
            int  id = sIx[t + off];
            if (s > sSc[t] || (s == sSc[t] && id < sIx[t])) { sSc[t] = s; sIx[t] = id; }
        }
        __syncthreads();
    }
    if (t == 0) { g_bScore[blockIdx.x] = sSc[0]; g_bIdx[blockIdx.x] = sIx[0]; }
}

// -------- finalize: global argmax over 391 blocks; maintain taken state -----
__global__ void finalize_kernel(int k) {
    __shared__ float sSc[256];
    __shared__ int   sIx[256];

    float best = -CUDART_INF_F;
    int   bi = 0x7fffffff;
    for (int i = threadIdx.x; i < DBLK; i += 256) {
        float s = g_bScore[i];
        int  id = g_bIdx[i];
        if (s > best || (s == best && id < bi)) { best = s; bi = id; }
    }
    sSc[threadIdx.x] = best;
    sIx[threadIdx.x] = bi;
    __syncthreads();
    for (int off = 128; off > 0; off >>= 1) {
        if (threadIdx.x < off) {
            float s = sSc[threadIdx.x + off];
            int  id = sIx[threadIdx.x + off];
            if (s > sSc[threadIdx.x] || (s == sSc[threadIdx.x] && id < sIx[threadIdx.x])) {
                sSc[threadIdx.x] = s;
                sIx[threadIdx.x] = id;
            }
        }
        __syncthreads();
    }
    if (threadIdx.x == 0) {
        int w = sIx[0];
        g_sel[k] = w;
        float t = g_taken[w];
        g_taken[w] = __fadd_rn(t, -100000.0f);
        if (t == 0.0f) {
            g_remaining -= 1;
            int n = g_nTaken;
            int pos = n;
            while (pos > 0 && g_takenList[pos - 1] > w) {
                g_takenList[pos] = g_takenList[pos - 1];
                pos--;
            }
            g_takenList[pos] = w;
            g_nTaken = n + 1;
        }
        g_restartSeg = w >> 10;   // chain changes from row w onward
    }
}

// -------- epilogue: rank sort (duplicate-safe), gather rows --------
__global__ void sortsel_kernel() {
    int t = threadIdx.x;            // 64 threads
    int v = g_sel[t];
    int r = 0;
    for (int j = 0; j < RNUM; j++) {
        int u = g_sel[j];
        r += (u < v) || (u == v && j < t);
    }
    g_selSorted[r] = v;
}

__global__ void gather_kernel(const float* __restrict__ x, float* __restrict__ out) {
    int row = g_selSorted[blockIdx.x];
    const float4* src = (const float4*)(x + (size_t)row * DIM);
    float4* dst = (float4*)(out + (size_t)blockIdx.x * DIM);
    dst[threadIdx.x] = src[threadIdx.x];   // 256 threads x float4 = 1024 floats
}

extern "C" void kernel_launch(void* const* d_in, const int* in_sizes, int n_in,
                              void* d_out, int out_size) {
    const float* x = (const float*)d_in[0];
    float* out = (float*)d_out;

    cudaFuncSetAttribute(colsum_kernel,
                         cudaFuncAttributeMaxDynamicSharedMemorySize, CS_SMEM);

    init_kernel<<<(NROWS + 255) / 256, 256>>>();

    for (int k = 0; k < RNUM; k++) {
        colsum_kernel<<<CS_BLOCKS, 256, CS_SMEM>>>(x);
        dots_argmax_kernel<<<DBLK, DR>>>(x);
        finalize_kernel<<<1, 256>>>(k);
    }

    sortsel_kernel<<<1, RNUM>>>();
    gather_kernel<<<RNUM, 256>>>(x, out);
}